// round 17
// baseline (speedup 1.0000x reference)
#include <cuda_runtime.h>
#include <math.h>
#include <cstdint>

#define BB 4
#define SS 2048
#define DM 1024
#define NH 16
#define DK 64
#define MM (BB*SS)   // 8192

// Scratch (allocation-free): __device__ globals
__device__ float g_q[BB*NH*SS*DK];      // [b,h,s,dk]
__device__ float g_k[BB*NH*SS*DK];
__device__ float g_v[BB*NH*SS*DK];
__device__ float g_att[MM*DM];          // [b,s,d] row-major
__device__ float2 g_rope[SS * 32];      // [s][i] = (cos, sin)

// ---------------------------------------------------------------------------
// tf32 + bf16 helpers
// ---------------------------------------------------------------------------
__device__ __forceinline__ uint32_t f2tf32(float f) {
    uint32_t r;
    asm("cvt.rna.tf32.f32 %0, %1;" : "=r"(r) : "f"(f));
    return r;
}
__device__ __forceinline__ void mma_tf32(float* c, const uint32_t* a, const uint32_t* b) {
    asm volatile(
        "mma.sync.aligned.m16n8k8.row.col.f32.tf32.tf32.f32 "
        "{%0,%1,%2,%3}, {%4,%5,%6,%7}, {%8,%9}, {%0,%1,%2,%3};"
        : "+f"(c[0]), "+f"(c[1]), "+f"(c[2]), "+f"(c[3])
        : "r"(a[0]), "r"(a[1]), "r"(a[2]), "r"(a[3]), "r"(b[0]), "r"(b[1]));
}
__device__ __forceinline__ uint32_t pack_bf16x2(float lo_elem, float hi_elem) {
    uint32_t r;
    asm("cvt.rn.bf16x2.f32 %0, %1, %2;" : "=r"(r) : "f"(hi_elem), "f"(lo_elem));
    return r;
}
__device__ __forceinline__ float bf_lo(uint32_t p) { return __uint_as_float(p << 16); }
__device__ __forceinline__ float bf_hi(uint32_t p) { return __uint_as_float(p & 0xffff0000u); }
__device__ __forceinline__ void split2(float x, float y, uint32_t& h, uint32_t& l) {
    h = pack_bf16x2(x, y);
    l = pack_bf16x2(x - bf_lo(h), y - bf_hi(h));
}
__device__ __forceinline__ void mma_bf16(float* c, const uint32_t* a, const uint32_t* b) {
    asm volatile(
        "mma.sync.aligned.m16n8k16.row.col.f32.bf16.bf16.f32 "
        "{%0,%1,%2,%3}, {%4,%5,%6,%7}, {%8,%9}, {%0,%1,%2,%3};"
        : "+f"(c[0]), "+f"(c[1]), "+f"(c[2]), "+f"(c[3])
        : "r"(a[0]), "r"(a[1]), "r"(a[2]), "r"(a[3]), "r"(b[0]), "r"(b[1]));
}

// ---------------------------------------------------------------------------
// RoPE cos/sin table build (deterministic; rebuilt each call).
// ---------------------------------------------------------------------------
__global__ void rope_table_kernel()
{
    int idx = blockIdx.x * 256 + threadIdx.x;   // 65536 entries
    int s = idx >> 5, i = idx & 31;
    float inv = powf(10000.0f, -(float)i / 32.0f);
    float sn, cs;
    sincosf((float)s * inv, &sn, &cs);
    g_rope[idx] = make_float2(cs, sn);
}

// ===========================================================================
// Fused QKV tf32 GEMM + RoPE epilogue. Tiles 128(m) x 64(n), BK=32, 256 thr.
// Grid (48, 64): blockIdx.x = nblk(16) + 16*mat(3). Warp grid 4m x 2n,
// warp tile 32x32. Scatter to [b,h,s,dk]; RoPE applied for mat<2 (q,k).
// ===========================================================================
#define SPITCH 36

__global__ __launch_bounds__(256) void qkv_kernel(const float* __restrict__ X,
                                                  const float* __restrict__ QW,
                                                  const float* __restrict__ KW,
                                                  const float* __restrict__ VW,
                                                  float* __restrict__ Qo,
                                                  float* __restrict__ Ko,
                                                  float* __restrict__ Vo)
{
    __shared__ uint32_t As[128 * SPITCH];
    __shared__ uint32_t Bs[64 * SPITCH];

    const int mat = blockIdx.x >> 4;
    const int n0 = (blockIdx.x & 15) * 64;
    const int m0 = blockIdx.y * 128;
    const float* W = (mat == 0) ? QW : (mat == 1) ? KW : VW;
    float* C = (mat == 0) ? Qo : (mat == 1) ? Ko : Vo;

    const int tid = threadIdx.x;
    const int wid = tid >> 5, lid = tid & 31;
    const int gid = lid >> 2, tig = lid & 3;
    const int wm = (wid & 3) * 32;
    const int wn = (wid >> 2) * 32;

    const int ldrow = tid >> 3;
    const int ldc4  = tid & 7;

    float acc[2][4][4] = {};
    float4 pa[4], pb[2];

#pragma unroll
    for (int i = 0; i < 4; i++)
        pa[i] = *(const float4*)(X + (size_t)(m0 + ldrow + i * 32) * DM + ldc4 * 4);
#pragma unroll
    for (int i = 0; i < 2; i++)
        pb[i] = *(const float4*)(W + (size_t)(n0 + ldrow + i * 32) * DM + ldc4 * 4);

    for (int it = 0; it < DM / 32; ++it) {
#pragma unroll
        for (int i = 0; i < 4; i++) {
            uint32_t off = (ldrow + i * 32) * SPITCH + ldc4 * 4;
            As[off+0] = f2tf32(pa[i].x); As[off+1] = f2tf32(pa[i].y);
            As[off+2] = f2tf32(pa[i].z); As[off+3] = f2tf32(pa[i].w);
        }
#pragma unroll
        for (int i = 0; i < 2; i++) {
            uint32_t off = (ldrow + i * 32) * SPITCH + ldc4 * 4;
            Bs[off+0] = f2tf32(pb[i].x); Bs[off+1] = f2tf32(pb[i].y);
            Bs[off+2] = f2tf32(pb[i].z); Bs[off+3] = f2tf32(pb[i].w);
        }
        __syncthreads();

        if (it + 1 < DM / 32) {
            int kk = (it + 1) * 32;
#pragma unroll
            for (int i = 0; i < 4; i++)
                pa[i] = *(const float4*)(X + (size_t)(m0 + ldrow + i * 32) * DM + kk + ldc4 * 4);
#pragma unroll
            for (int i = 0; i < 2; i++)
                pb[i] = *(const float4*)(W + (size_t)(n0 + ldrow + i * 32) * DM + kk + ldc4 * 4);
        }

#pragma unroll
        for (int ks = 0; ks < 4; ks++) {
            const int k0 = ks * 8;
            uint32_t a[2][4], b[4][2];
#pragma unroll
            for (int mt = 0; mt < 2; mt++) {
                int r = wm + mt * 16 + gid;
                a[mt][0] = As[r * SPITCH + k0 + tig];
                a[mt][1] = As[(r + 8) * SPITCH + k0 + tig];
                a[mt][2] = As[r * SPITCH + k0 + tig + 4];
                a[mt][3] = As[(r + 8) * SPITCH + k0 + tig + 4];
            }
#pragma unroll
            for (int nt = 0; nt < 4; nt++) {
                int cn = wn + nt * 8 + gid;
                b[nt][0] = Bs[cn * SPITCH + k0 + tig];
                b[nt][1] = Bs[cn * SPITCH + k0 + tig + 4];
            }
#pragma unroll
            for (int mt = 0; mt < 2; mt++)
#pragma unroll
                for (int nt = 0; nt < 4; nt++)
                    mma_tf32(acc[mt][nt], a[mt], b[nt]);
        }
        __syncthreads();
    }

    const bool dorope = (mat < 2);
#pragma unroll
    for (int mt = 0; mt < 2; mt++) {
#pragma unroll
        for (int nt = 0; nt < 4; nt++) {
            int m = m0 + wm + mt * 16 + gid;
            int n = n0 + wn + nt * 8 + 2 * tig;
            float2 lo = make_float2(acc[mt][nt][0], acc[mt][nt][1]);
            float2 hi = make_float2(acc[mt][nt][2], acc[mt][nt][3]);
            if (dorope) {
                int i = (n & 63) >> 1;
                float2 c1 = g_rope[(m & 2047) * 32 + i];
                float2 c2 = g_rope[((m + 8) & 2047) * 32 + i];
                lo = make_float2(lo.x * c1.x - lo.y * c1.y, lo.x * c1.y + lo.y * c1.x);
                hi = make_float2(hi.x * c2.x - hi.y * c2.y, hi.x * c2.y + hi.y * c2.x);
            }
            int h = n >> 6, d = n & 63;
            int b1 = m >> 11, s1 = m & 2047;
            int m2 = m + 8;
            int b2 = m2 >> 11, s2 = m2 & 2047;
            *(float2*)(C + (((size_t)((b1 << 4) + h)) * SS + s1) * DK + d) = lo;
            *(float2*)(C + (((size_t)((b2 << 4) + h)) * SS + s2) * DK + d) = hi;
        }
    }
}

// ===========================================================================
// o_proj tf32 GEMM: C = A @ W^T, row-major out. Tiles 128x64, grid (16,64).
// ===========================================================================
__global__ __launch_bounds__(256) void oproj_kernel(const float* __restrict__ A,
                                                    const float* __restrict__ W,
                                                    float* __restrict__ C)
{
    __shared__ uint32_t As[128 * SPITCH];
    __shared__ uint32_t Bs[64 * SPITCH];

    const int n0 = blockIdx.x * 64;
    const int m0 = blockIdx.y * 128;

    const int tid = threadIdx.x;
    const int wid = tid >> 5, lid = tid & 31;
    const int gid = lid >> 2, tig = lid & 3;
    const int wm = (wid & 3) * 32;
    const int wn = (wid >> 2) * 32;

    const int ldrow = tid >> 3;
    const int ldc4  = tid & 7;

    float acc[2][4][4] = {};
    float4 pa[4], pb[2];

#pragma unroll
    for (int i = 0; i < 4; i++)
        pa[i] = *(const float4*)(A + (size_t)(m0 + ldrow + i * 32) * DM + ldc4 * 4);
#pragma unroll
    for (int i = 0; i < 2; i++)
        pb[i] = *(const float4*)(W + (size_t)(n0 + ldrow + i * 32) * DM + ldc4 * 4);

    for (int it = 0; it < DM / 32; ++it) {
#pragma unroll
        for (int i = 0; i < 4; i++) {
            uint32_t off = (ldrow + i * 32) * SPITCH + ldc4 * 4;
            As[off+0] = f2tf32(pa[i].x); As[off+1] = f2tf32(pa[i].y);
            As[off+2] = f2tf32(pa[i].z); As[off+3] = f2tf32(pa[i].w);
        }
#pragma unroll
        for (int i = 0; i < 2; i++) {
            uint32_t off = (ldrow + i * 32) * SPITCH + ldc4 * 4;
            Bs[off+0] = f2tf32(pb[i].x); Bs[off+1] = f2tf32(pb[i].y);
            Bs[off+2] = f2tf32(pb[i].z); Bs[off+3] = f2tf32(pb[i].w);
        }
        __syncthreads();

        if (it + 1 < DM / 32) {
            int kk = (it + 1) * 32;
#pragma unroll
            for (int i = 0; i < 4; i++)
                pa[i] = *(const float4*)(A + (size_t)(m0 + ldrow + i * 32) * DM + kk + ldc4 * 4);
#pragma unroll
            for (int i = 0; i < 2; i++)
                pb[i] = *(const float4*)(W + (size_t)(n0 + ldrow + i * 32) * DM + kk + ldc4 * 4);
        }

#pragma unroll
        for (int ks = 0; ks < 4; ks++) {
            const int k0 = ks * 8;
            uint32_t a[2][4], b[4][2];
#pragma unroll
            for (int mt = 0; mt < 2; mt++) {
                int r = wm + mt * 16 + gid;
                a[mt][0] = As[r * SPITCH + k0 + tig];
                a[mt][1] = As[(r + 8) * SPITCH + k0 + tig];
                a[mt][2] = As[r * SPITCH + k0 + tig + 4];
                a[mt][3] = As[(r + 8) * SPITCH + k0 + tig + 4];
            }
#pragma unroll
            for (int nt = 0; nt < 4; nt++) {
                int cn = wn + nt * 8 + gid;
                b[nt][0] = Bs[cn * SPITCH + k0 + tig];
                b[nt][1] = Bs[cn * SPITCH + k0 + tig + 4];
            }
#pragma unroll
            for (int mt = 0; mt < 2; mt++)
#pragma unroll
                for (int nt = 0; nt < 4; nt++)
                    mma_tf32(acc[mt][nt], a[mt], b[nt]);
        }
        __syncthreads();
    }

#pragma unroll
    for (int mt = 0; mt < 2; mt++) {
#pragma unroll
        for (int nt = 0; nt < 4; nt++) {
            int m = m0 + wm + mt * 16 + gid;
            int n = n0 + wn + nt * 8 + 2 * tig;
            *(float2*)(C + (size_t)m * DM + n) =
                make_float2(acc[mt][nt][0], acc[mt][nt][1]);
            *(float2*)(C + (size_t)(m + 8) * DM + n) =
                make_float2(acc[mt][nt][2], acc[mt][nt][3]);
        }
    }
}

// ===========================================================================
// Split-bf16 causal flash attention (R12, measured; 3-term, fp32-grade).
// Grid: (32 qtiles, 64 bh). Block 128 = 4 warps x 16 q-rows.
// S C-frag == PV A-frag for m16n8k16 -> zero shuffles.
// ===========================================================================
#define KP2 36   // Ks pitch: frag bank = (4*gid+tig), bijective
#define VTP 20   // Vt pitch: frag bank = (20*gid+tig)%32, bijective

__global__ __launch_bounds__(128) void fattn_kernel(const float* __restrict__ Q,
                                                    const float* __restrict__ K,
                                                    const float* __restrict__ V,
                                                    float* __restrict__ O)
{
    __shared__ uint32_t Kh[32 * KP2], Kl[32 * KP2];
    __shared__ uint32_t Vth[64 * VTP], Vtl[64 * VTP];

    const int tid = threadIdx.x, wid = tid >> 5, lid = tid & 31;
    const int gid = lid >> 2, tig = lid & 3;
    const int qt = 31 - blockIdx.x;          // heavy tiles first
    const int bh = blockIdx.y;
    const int h = bh & 15, b = bh >> 4;
    const int wrow = qt * 64 + wid * 16 + gid;

    const float* Qb = Q + (size_t)bh * SS * DK;
    const float* Kb = K + (size_t)bh * SS * DK;
    const float* Vb = V + (size_t)bh * SS * DK;

    // Hoist Q A-fragments (hi/lo) for 4 k16-steps
    uint32_t qh[4][4], ql[4][4];
    {
        const float* r0 = Qb + (size_t)wrow * DK;
        const float* r1 = r0 + 8 * DK;
#pragma unroll
        for (int ks = 0; ks < 4; ks++) {
            int d0 = ks * 16 + 2 * tig;
            float2 x0 = *(const float2*)(r0 + d0);
            float2 x1 = *(const float2*)(r1 + d0);
            float2 x2 = *(const float2*)(r0 + d0 + 8);
            float2 x3 = *(const float2*)(r1 + d0 + 8);
            split2(x0.x, x0.y, qh[ks][0], ql[ks][0]);
            split2(x1.x, x1.y, qh[ks][1], ql[ks][1]);
            split2(x2.x, x2.y, qh[ks][2], ql[ks][2]);
            split2(x3.x, x3.y, qh[ks][3], ql[ks][3]);
        }
    }

    float oacc[8][4] = {};
    float m0 = -1e30f, m1 = -1e30f, l0 = 0.0f, l1 = 0.0f;

    const int ntiles = 2 * qt + 2;
    for (int t = 0; t < ntiles; t++) {
        const int kv0 = t * 32;
        const bool domask = (t >= 2 * qt);
        __syncthreads();

        // Stage K tile: [32 kv][64 dk] -> bf16x2 dk-pairs
#pragma unroll
        for (int j = 0; j < 4; j++) {
            int id = tid + j * 128;
            int kv = id >> 4, c = id & 15;
            float4 kf = *(const float4*)(Kb + (size_t)(kv0 + kv) * DK + c * 4);
            uint32_t h0, L0, h1, L1;
            split2(kf.x, kf.y, h0, L0);
            split2(kf.z, kf.w, h1, L1);
            uint32_t off = kv * KP2 + 2 * c;
            Kh[off] = h0; Kh[off + 1] = h1;
            Kl[off] = L0; Kl[off + 1] = L1;
        }
        // Stage V tile TRANSPOSED: pairs along kv -> Vt[d][kv/2]
#pragma unroll
        for (int j = 0; j < 2; j++) {
            int id = tid + j * 128;
            int p = id & 15, c = id >> 4;
            float4 v0 = *(const float4*)(Vb + (size_t)(kv0 + 2 * p) * DK + c * 4);
            float4 v1 = *(const float4*)(Vb + (size_t)(kv0 + 2 * p + 1) * DK + c * 4);
            float e0[4] = {v0.x, v0.y, v0.z, v0.w};
            float e1[4] = {v1.x, v1.y, v1.z, v1.w};
#pragma unroll
            for (int e = 0; e < 4; e++) {
                uint32_t hh, ll;
                split2(e0[e], e1[e], hh, ll);
                Vth[(4 * c + e) * VTP + p] = hh;
                Vtl[(4 * c + e) * VTP + p] = ll;
            }
        }
        __syncthreads();

        // ---- S = Q K^T (3-term split-bf16) ----
        float sfr[4][4] = {};
#pragma unroll
        for (int ks = 0; ks < 4; ks++) {
#pragma unroll
            for (int nt = 0; nt < 4; nt++) {
                int base = (nt * 8 + gid) * KP2 + ks * 8 + tig;
                uint32_t BH[2] = { Kh[base], Kh[base + 4] };
                uint32_t BL[2] = { Kl[base], Kl[base + 4] };
                mma_bf16(sfr[nt], qh[ks], BH);
                mma_bf16(sfr[nt], qh[ks], BL);
                mma_bf16(sfr[nt], ql[ks], BH);
            }
        }

        // ---- scale + mask + online softmax ----
        float tm0 = -1e30f, tm1 = -1e30f;
#pragma unroll
        for (int nt = 0; nt < 4; nt++) {
            int c = kv0 + nt * 8 + 2 * tig;
            float v0 = sfr[nt][0] * 0.125f;
            float v1 = sfr[nt][1] * 0.125f;
            float v2 = sfr[nt][2] * 0.125f;
            float v3 = sfr[nt][3] * 0.125f;
            if (domask) {
                if (c     > wrow)     v0 = -1e30f;
                if (c + 1 > wrow)     v1 = -1e30f;
                if (c     > wrow + 8) v2 = -1e30f;
                if (c + 1 > wrow + 8) v3 = -1e30f;
            }
            sfr[nt][0] = v0; sfr[nt][1] = v1; sfr[nt][2] = v2; sfr[nt][3] = v3;
            tm0 = fmaxf(tm0, fmaxf(v0, v1));
            tm1 = fmaxf(tm1, fmaxf(v2, v3));
        }
        tm0 = fmaxf(tm0, __shfl_xor_sync(0xffffffffu, tm0, 1));
        tm0 = fmaxf(tm0, __shfl_xor_sync(0xffffffffu, tm0, 2));
        tm1 = fmaxf(tm1, __shfl_xor_sync(0xffffffffu, tm1, 1));
        tm1 = fmaxf(tm1, __shfl_xor_sync(0xffffffffu, tm1, 2));

        float mn0 = fmaxf(m0, tm0), mn1 = fmaxf(m1, tm1);
        float a0 = __expf(m0 - mn0), a1 = __expf(m1 - mn1);
        float s0 = 0.0f, s1 = 0.0f;
#pragma unroll
        for (int nt = 0; nt < 4; nt++) {
            float p0 = __expf(sfr[nt][0] - mn0);
            float p1 = __expf(sfr[nt][1] - mn0);
            float p2 = __expf(sfr[nt][2] - mn1);
            float p3 = __expf(sfr[nt][3] - mn1);
            sfr[nt][0] = p0; sfr[nt][1] = p1; sfr[nt][2] = p2; sfr[nt][3] = p3;
            s0 += p0 + p1; s1 += p2 + p3;
        }
        s0 += __shfl_xor_sync(0xffffffffu, s0, 1);
        s0 += __shfl_xor_sync(0xffffffffu, s0, 2);
        s1 += __shfl_xor_sync(0xffffffffu, s1, 1);
        s1 += __shfl_xor_sync(0xffffffffu, s1, 2);
        l0 = l0 * a0 + s0; l1 = l1 * a1 + s1;
        m0 = mn0; m1 = mn1;
#pragma unroll
        for (int nt = 0; nt < 8; nt++) {
            oacc[nt][0] *= a0; oacc[nt][1] *= a0;
            oacc[nt][2] *= a1; oacc[nt][3] *= a1;
        }

        // ---- O += P V (3-term split-bf16): S C-frag IS the PV A-frag ----
#pragma unroll
        for (int Ks = 0; Ks < 2; Ks++) {
            uint32_t ph[4], pl[4];
            split2(sfr[2*Ks][0],     sfr[2*Ks][1],     ph[0], pl[0]);
            split2(sfr[2*Ks][2],     sfr[2*Ks][3],     ph[1], pl[1]);
            split2(sfr[2*Ks + 1][0], sfr[2*Ks + 1][1], ph[2], pl[2]);
            split2(sfr[2*Ks + 1][2], sfr[2*Ks + 1][3], ph[3], pl[3]);
#pragma unroll
            for (int nt = 0; nt < 8; nt++) {
                int base = (nt * 8 + gid) * VTP + Ks * 8 + tig;
                uint32_t BH[2] = { Vth[base], Vth[base + 4] };
                uint32_t BL[2] = { Vtl[base], Vtl[base + 4] };
                mma_bf16(oacc[nt], ph, BH);
                mma_bf16(oacc[nt], ph, BL);
                mma_bf16(oacc[nt], pl, BH);
            }
        }
    }

    // ---- epilogue ----
    float i0 = 1.0f / l0, i1 = 1.0f / l1;
    float* o0 = O + ((size_t)b * SS + wrow) * DM + h * 64;
    float* o1 = o0 + 8 * DM;
#pragma unroll
    for (int nt = 0; nt < 8; nt++) {
        *(float2*)(o0 + nt * 8 + 2 * tig) =
            make_float2(oacc[nt][0] * i0, oacc[nt][1] * i0);
        *(float2*)(o1 + nt * 8 + 2 * tig) =
            make_float2(oacc[nt][2] * i1, oacc[nt][3] * i1);
    }
}

// ---------------------------------------------------------------------------
extern "C" void kernel_launch(void* const* d_in, const int* in_sizes, int n_in,
                              void* d_out, int out_size)
{
    const float* x  = (const float*)d_in[0];
    const float* qw = (const float*)d_in[1];
    const float* kw = (const float*)d_in[2];
    const float* vw = (const float*)d_in[3];
    const float* ow = (const float*)d_in[4];
    float* out = (float*)d_out;

    float *q, *k, *v, *att;
    cudaGetSymbolAddress((void**)&q,   g_q);
    cudaGetSymbolAddress((void**)&k,   g_k);
    cudaGetSymbolAddress((void**)&v,   g_v);
    cudaGetSymbolAddress((void**)&att, g_att);

    rope_table_kernel<<<256, 256>>>();
    qkv_kernel<<<dim3(48, 64), 256>>>(x, qw, kw, vw, q, k, v);
    fattn_kernel<<<dim3(32, 64), 128>>>(q, k, v, att);
    oproj_kernel<<<dim3(16, 64), 256>>>(att, ow, out);
}